// round 7
// baseline (speedup 1.0000x reference)
#include <cuda_runtime.h>

#define NN 50000
#define EE 200000
#define IND 768
#define HIDD 256
#define OUTD 64
#define NHEAD 4
#define DH 64
#define RELS 6
#define NEG 0.2f
#define LNEPS 1e-5f

// ---------------- scratch (static device globals; no allocs) ----------------
__device__ float g_h1[(size_t)NN * HIDD];     // x_mod @ W1
__device__ float g_agg1[(size_t)NN * HIDD];   // layer1 aggregation, then LN+ELU in place
__device__ float g_embW1[RELS * HIDD];        // edge_emb @ W1
__device__ int   g_winner[NN];                // last edge id with src==node, else -1
__device__ float g_als1[NN * NHEAD], g_ald1[NN * NHEAD];
__device__ unsigned g_emax1[NN * NHEAD];
__device__ float g_denom1[NN * NHEAD];
__device__ float g_ex1[(size_t)EE * NHEAD];
__device__ float g_z[(size_t)NN * OUTD];      // h2 @ W2
__device__ float g_als2[NN], g_ald2[NN];
__device__ unsigned g_emax2[NN];
__device__ float g_denom2[NN];
__device__ float g_ex2[EE];
// converted edge arrays (int32), robust to int32/int64 input dtype
__device__ int g_src[EE], g_dst[EE], g_et[EE];
__device__ int g_is64;                         // 1 if inputs are int64

// ---------------- helpers ----------------
__device__ __forceinline__ unsigned fkey(float f) {
    unsigned b = __float_as_uint(f);
    return (b & 0x80000000u) ? ~b : (b | 0x80000000u);
}
__device__ __forceinline__ float funkey(unsigned k) {
    unsigned b = (k & 0x80000000u) ? (k & 0x7FFFFFFFu) : ~k;
    return __uint_as_float(b);
}

// ---------------- dtype detect + convert ----------------
// If edge_index is int64 (node ids < 2^31), every odd 32-bit word is 0.
// If int32, odd words are random node ids. 256 samples decide.
__global__ void k_detect(const int* __restrict__ ei32) {
    __shared__ int any_nz;
    if (threadIdx.x == 0) any_nz = 0;
    __syncthreads();
    if (ei32[2 * threadIdx.x + 1] != 0) atomicOr(&any_nz, 1);
    __syncthreads();
    if (threadIdx.x == 0) g_is64 = (any_nz == 0) ? 1 : 0;
}

__global__ void k_convert(const int* __restrict__ ei32, const int* __restrict__ et32) {
    int e = blockIdx.x * blockDim.x + threadIdx.x;
    if (e >= EE) return;
    if (g_is64) {
        g_src[e] = ei32[2 * e];
        g_dst[e] = ei32[2 * (EE + e)];
        g_et[e]  = et32[2 * e];
    } else {
        g_src[e] = ei32[e];
        g_dst[e] = ei32[EE + e];
        g_et[e]  = et32[e];
    }
}

// ---------------- init ----------------
__global__ void k_init(float* __restrict__ out) {
    size_t i = (size_t)blockIdx.x * blockDim.x + threadIdx.x;
    if (i < (size_t)NN * HIDD) g_agg1[i] = 0.f;
    if (i < (size_t)NN * OUTD) out[i] = 0.f;
    if (i < NN * NHEAD) { g_denom1[i] = 0.f; g_emax1[i] = 0u; }
    if (i < NN) { g_winner[i] = -1; g_denom2[i] = 0.f; g_emax2[i] = 0u; }
}

__global__ void k_winner() {
    int e = blockIdx.x * blockDim.x + threadIdx.x;
    if (e >= EE) return;
    atomicMax(&g_winner[g_src[e]], e);
}

// edge_emb @ W1 -> [RELS, HIDD]
__global__ void k_embw(const float* __restrict__ emb, const float* __restrict__ W1) {
    int r = blockIdx.x, c = threadIdx.x;
    float s = 0.f;
#pragma unroll 8
    for (int k = 0; k < IND; k++) s += emb[r * IND + k] * W1[(size_t)k * HIDD + c];
    g_embW1[r * HIDD + c] = s;
}

// ---------------- GEMM1: h1 = x @ W1 (+ winner delta) ----------------
// 128x128 tile, BK=16, 256 threads, 8x8 microtile (scalar FFMA).
__global__ __launch_bounds__(256, 2)
void k_gemm1(const float* __restrict__ A, const float* __restrict__ B) {
    __shared__ float As[16][128];
    __shared__ float Bs[16][128];
    const int tid = threadIdx.x;
    const int tx = tid & 15, ty = tid >> 4;
    const int bm = blockIdx.y * 128, bn = blockIdx.x * 128;

    float acc[8][8];
#pragma unroll
    for (int m = 0; m < 8; m++)
#pragma unroll
        for (int j = 0; j < 8; j++) acc[m][j] = 0.f;

    float4 pa[2], pb[2];
#pragma unroll
    for (int i = 0; i < 2; i++) {
        int s = tid * 2 + i;
        int row = s >> 2, kc = (s & 3) * 4;
        int gr = bm + row;
        pa[i] = make_float4(0.f, 0.f, 0.f, 0.f);
        if (gr < NN) pa[i] = *(const float4*)&A[(size_t)gr * IND + kc];
        int kr = s >> 5, nc = (s & 31) * 4;
        pb[i] = *(const float4*)&B[(size_t)kr * HIDD + bn + nc];
    }
#pragma unroll
    for (int i = 0; i < 2; i++) {
        int s = tid * 2 + i;
        int row = s >> 2, kc = (s & 3) * 4;
        As[kc + 0][row] = pa[i].x; As[kc + 1][row] = pa[i].y;
        As[kc + 2][row] = pa[i].z; As[kc + 3][row] = pa[i].w;
        int kr = s >> 5, nc = (s & 31) * 4;
        *(float4*)&Bs[kr][nc] = pb[i];
    }
    __syncthreads();

    for (int kt = 0; kt < 48; kt++) {
        if (kt < 47) {
            int k0 = (kt + 1) * 16;
#pragma unroll
            for (int i = 0; i < 2; i++) {
                int s = tid * 2 + i;
                int row = s >> 2, kc = (s & 3) * 4;
                int gr = bm + row;
                pa[i] = make_float4(0.f, 0.f, 0.f, 0.f);
                if (gr < NN) pa[i] = *(const float4*)&A[(size_t)gr * IND + k0 + kc];
                int kr = s >> 5, nc = (s & 31) * 4;
                pb[i] = *(const float4*)&B[(size_t)(k0 + kr) * HIDD + bn + nc];
            }
        }
#pragma unroll
        for (int k = 0; k < 16; k++) {
            float4 b0 = *(const float4*)&Bs[k][tx * 8];
            float4 b1 = *(const float4*)&Bs[k][tx * 8 + 4];
            float4 a0 = *(const float4*)&As[k][ty * 8];
            float4 a1 = *(const float4*)&As[k][ty * 8 + 4];
            float av[8] = {a0.x, a0.y, a0.z, a0.w, a1.x, a1.y, a1.z, a1.w};
            float bv[8] = {b0.x, b0.y, b0.z, b0.w, b1.x, b1.y, b1.z, b1.w};
#pragma unroll
            for (int m = 0; m < 8; m++)
#pragma unroll
                for (int j = 0; j < 8; j++)
                    acc[m][j] = fmaf(av[m], bv[j], acc[m][j]);
        }
        __syncthreads();
        if (kt < 47) {
#pragma unroll
            for (int i = 0; i < 2; i++) {
                int s = tid * 2 + i;
                int row = s >> 2, kc = (s & 3) * 4;
                As[kc + 0][row] = pa[i].x; As[kc + 1][row] = pa[i].y;
                As[kc + 2][row] = pa[i].z; As[kc + 3][row] = pa[i].w;
                int kr = s >> 5, nc = (s & 31) * 4;
                *(float4*)&Bs[kr][nc] = pb[i];
            }
        }
        __syncthreads();
    }

    // epilogue: add edge-emb delta for winner rows, write h1
#pragma unroll
    for (int m = 0; m < 8; m++) {
        int gr = bm + ty * 8 + m;
        if (gr >= NN) continue;
        int w = g_winner[gr];
        int t = (w >= 0) ? g_et[w] : -1;
#pragma unroll
        for (int j = 0; j < 8; j++) {
            int col = bn + tx * 8 + j;
            float v = acc[m][j];
            if (t >= 0) v += g_embW1[t * HIDD + col];
            g_h1[(size_t)gr * HIDD + col] = v;
        }
    }
}

// ---------------- layer 1 attention ----------------
__global__ void k_logits1(const float* __restrict__ as1, const float* __restrict__ ad1) {
    int n = blockIdx.x;
    int h = threadIdx.x >> 5, l = threadIdx.x & 31;
    float v0 = g_h1[(size_t)n * HIDD + h * DH + l];
    float v1 = g_h1[(size_t)n * HIDD + h * DH + 32 + l];
    float s = v0 * as1[h * DH + l] + v1 * as1[h * DH + 32 + l];
    float d = v0 * ad1[h * DH + l] + v1 * ad1[h * DH + 32 + l];
#pragma unroll
    for (int o = 16; o; o >>= 1) {
        s += __shfl_xor_sync(0xffffffffu, s, o);
        d += __shfl_xor_sync(0xffffffffu, d, o);
    }
    if (l == 0) { g_als1[n * NHEAD + h] = s; g_ald1[n * NHEAD + h] = d; }
}

__global__ void k_max1() {
    int idx = blockIdx.x * blockDim.x + threadIdx.x;
    if (idx >= EE * NHEAD) return;
    int e = idx >> 2, h = idx & 3;
    int s = g_src[e], d = g_dst[e];
    float ev = g_als1[s * NHEAD + h] + g_ald1[d * NHEAD + h];
    ev = (ev >= 0.f) ? ev : NEG * ev;
    atomicMax(&g_emax1[d * NHEAD + h], fkey(ev));
}

__global__ void k_sum1() {
    int idx = blockIdx.x * blockDim.x + threadIdx.x;
    if (idx >= EE * NHEAD) return;
    int e = idx >> 2, h = idx & 3;
    int s = g_src[e], d = g_dst[e];
    float ev = g_als1[s * NHEAD + h] + g_ald1[d * NHEAD + h];
    ev = (ev >= 0.f) ? ev : NEG * ev;
    float ex = expf(ev - funkey(g_emax1[d * NHEAD + h]));
    atomicAdd(&g_denom1[d * NHEAD + h], ex);
    g_ex1[(size_t)e * NHEAD + h] = ex;
}

// block (256 threads) per edge: agg1[dst] += h1[src] * alpha
__global__ void k_agg1() {
    int e = blockIdx.x;
    __shared__ float al[NHEAD];
    int ss = g_src[e], dd = g_dst[e];
    if (threadIdx.x < NHEAD)
        al[threadIdx.x] = g_ex1[(size_t)e * NHEAD + threadIdx.x] /
                          g_denom1[dd * NHEAD + threadIdx.x];
    __syncthreads();
    int f = threadIdx.x;
    atomicAdd(&g_agg1[(size_t)dd * HIDD + f], g_h1[(size_t)ss * HIDD + f] * al[f >> 6]);
}

// warp per node: +b1, LayerNorm, ELU (in place on g_agg1)
__global__ void k_ln1(const float* __restrict__ b1, const float* __restrict__ g1,
                      const float* __restrict__ be1) {
    int n = blockIdx.x * 4 + (threadIdx.x >> 5);
    if (n >= NN) return;
    int l = threadIdx.x & 31;
    float v[8]; float sum = 0.f;
#pragma unroll
    for (int i = 0; i < 8; i++) {
        v[i] = g_agg1[(size_t)n * HIDD + i * 32 + l] + b1[i * 32 + l];
        sum += v[i];
    }
#pragma unroll
    for (int o = 16; o; o >>= 1) sum += __shfl_xor_sync(0xffffffffu, sum, o);
    float mu = sum * (1.f / HIDD);
    float s2 = 0.f;
#pragma unroll
    for (int i = 0; i < 8; i++) { v[i] -= mu; s2 += v[i] * v[i]; }
#pragma unroll
    for (int o = 16; o; o >>= 1) s2 += __shfl_xor_sync(0xffffffffu, s2, o);
    float r = rsqrtf(s2 * (1.f / HIDD) + LNEPS);
#pragma unroll
    for (int i = 0; i < 8; i++) {
        float y = v[i] * r * g1[i * 32 + l] + be1[i * 32 + l];
        g_agg1[(size_t)n * HIDD + i * 32 + l] = (y > 0.f) ? y : expm1f(y);
    }
}

// ---------------- GEMM2: z = h2 @ W2  (128x64 tile, BK=16) ----------------
__global__ __launch_bounds__(256, 2)
void k_gemm2(const float* __restrict__ B) {
    __shared__ float As[16][128];
    __shared__ float Bs[16][64];
    const float* A = g_agg1;
    const int tid = threadIdx.x;
    const int tx = tid & 15, ty = tid >> 4;
    const int bm = blockIdx.y * 128;

    float acc[8][4];
#pragma unroll
    for (int m = 0; m < 8; m++)
#pragma unroll
        for (int j = 0; j < 4; j++) acc[m][j] = 0.f;

    float4 pa[2], pb;
#pragma unroll
    for (int i = 0; i < 2; i++) {
        int s = tid * 2 + i;
        int row = s >> 2, kc = (s & 3) * 4;
        int gr = bm + row;
        pa[i] = make_float4(0.f, 0.f, 0.f, 0.f);
        if (gr < NN) pa[i] = *(const float4*)&A[(size_t)gr * HIDD + kc];
    }
    { int kr = tid >> 4, nc = (tid & 15) * 4;
      pb = *(const float4*)&B[(size_t)kr * OUTD + nc]; }
#pragma unroll
    for (int i = 0; i < 2; i++) {
        int s = tid * 2 + i;
        int row = s >> 2, kc = (s & 3) * 4;
        As[kc + 0][row] = pa[i].x; As[kc + 1][row] = pa[i].y;
        As[kc + 2][row] = pa[i].z; As[kc + 3][row] = pa[i].w;
    }
    { int kr = tid >> 4, nc = (tid & 15) * 4; *(float4*)&Bs[kr][nc] = pb; }
    __syncthreads();

    for (int kt = 0; kt < 16; kt++) {
        if (kt < 15) {
            int k0 = (kt + 1) * 16;
#pragma unroll
            for (int i = 0; i < 2; i++) {
                int s = tid * 2 + i;
                int row = s >> 2, kc = (s & 3) * 4;
                int gr = bm + row;
                pa[i] = make_float4(0.f, 0.f, 0.f, 0.f);
                if (gr < NN) pa[i] = *(const float4*)&A[(size_t)gr * HIDD + k0 + kc];
            }
            { int kr = tid >> 4, nc = (tid & 15) * 4;
              pb = *(const float4*)&B[(size_t)(k0 + kr) * OUTD + nc]; }
        }
#pragma unroll
        for (int k = 0; k < 16; k++) {
            float4 b0 = *(const float4*)&Bs[k][tx * 4];
            float4 a0 = *(const float4*)&As[k][ty * 8];
            float4 a1 = *(const float4*)&As[k][ty * 8 + 4];
            float av[8] = {a0.x, a0.y, a0.z, a0.w, a1.x, a1.y, a1.z, a1.w};
            float bv[4] = {b0.x, b0.y, b0.z, b0.w};
#pragma unroll
            for (int m = 0; m < 8; m++)
#pragma unroll
                for (int j = 0; j < 4; j++)
                    acc[m][j] = fmaf(av[m], bv[j], acc[m][j]);
        }
        __syncthreads();
        if (kt < 15) {
#pragma unroll
            for (int i = 0; i < 2; i++) {
                int s = tid * 2 + i;
                int row = s >> 2, kc = (s & 3) * 4;
                As[kc + 0][row] = pa[i].x; As[kc + 1][row] = pa[i].y;
                As[kc + 2][row] = pa[i].z; As[kc + 3][row] = pa[i].w;
            }
            { int kr = tid >> 4, nc = (tid & 15) * 4; *(float4*)&Bs[kr][nc] = pb; }
        }
        __syncthreads();
    }

#pragma unroll
    for (int m = 0; m < 8; m++) {
        int gr = bm + ty * 8 + m;
        if (gr >= NN) continue;
        float4 v = make_float4(acc[m][0], acc[m][1], acc[m][2], acc[m][3]);
        *(float4*)&g_z[(size_t)gr * OUTD + tx * 4] = v;
    }
}

// ---------------- layer 2 attention ----------------
__global__ void k_logits2(const float* __restrict__ as2, const float* __restrict__ ad2) {
    int n = blockIdx.x * 4 + (threadIdx.x >> 5);
    if (n >= NN) return;
    int l = threadIdx.x & 31;
    float v0 = g_z[(size_t)n * OUTD + l];
    float v1 = g_z[(size_t)n * OUTD + 32 + l];
    float s = v0 * as2[l] + v1 * as2[32 + l];
    float d = v0 * ad2[l] + v1 * ad2[32 + l];
#pragma unroll
    for (int o = 16; o; o >>= 1) {
        s += __shfl_xor_sync(0xffffffffu, s, o);
        d += __shfl_xor_sync(0xffffffffu, d, o);
    }
    if (l == 0) { g_als2[n] = s; g_ald2[n] = d; }
}

__global__ void k_max2() {
    int e = blockIdx.x * blockDim.x + threadIdx.x;
    if (e >= EE) return;
    int s = g_src[e], d = g_dst[e];
    float ev = g_als2[s] + g_ald2[d];
    ev = (ev >= 0.f) ? ev : NEG * ev;
    atomicMax(&g_emax2[d], fkey(ev));
}

__global__ void k_sum2() {
    int e = blockIdx.x * blockDim.x + threadIdx.x;
    if (e >= EE) return;
    int s = g_src[e], d = g_dst[e];
    float ev = g_als2[s] + g_ald2[d];
    ev = (ev >= 0.f) ? ev : NEG * ev;
    float ex = expf(ev - funkey(g_emax2[d]));
    atomicAdd(&g_denom2[d], ex);
    g_ex2[e] = ex;
}

__global__ void k_agg2(float* __restrict__ out) {
    int idx = blockIdx.x * blockDim.x + threadIdx.x;
    if (idx >= EE * OUTD) return;
    int e = idx >> 6, f = idx & 63;
    int s = g_src[e], d = g_dst[e];
    float alpha = g_ex2[e] / g_denom2[d];
    atomicAdd(&out[(size_t)d * OUTD + f], g_z[(size_t)s * OUTD + f] * alpha);
}

// warp per node: +b2, LayerNorm -> final out (in place)
__global__ void k_ln2(const float* __restrict__ b2, const float* __restrict__ g2,
                      const float* __restrict__ be2, float* __restrict__ out) {
    int n = blockIdx.x * 4 + (threadIdx.x >> 5);
    if (n >= NN) return;
    int l = threadIdx.x & 31;
    float v0 = out[(size_t)n * OUTD + l] + b2[l];
    float v1 = out[(size_t)n * OUTD + 32 + l] + b2[32 + l];
    float sum = v0 + v1;
#pragma unroll
    for (int o = 16; o; o >>= 1) sum += __shfl_xor_sync(0xffffffffu, sum, o);
    float mu = sum * (1.f / OUTD);
    v0 -= mu; v1 -= mu;
    float s2 = v0 * v0 + v1 * v1;
#pragma unroll
    for (int o = 16; o; o >>= 1) s2 += __shfl_xor_sync(0xffffffffu, s2, o);
    float r = rsqrtf(s2 * (1.f / OUTD) + LNEPS);
    out[(size_t)n * OUTD + l]      = v0 * r * g2[l] + be2[l];
    out[(size_t)n * OUTD + 32 + l] = v1 * r * g2[32 + l] + be2[32 + l];
}

// ---------------- launch ----------------
extern "C" void kernel_launch(void* const* d_in, const int* in_sizes, int n_in,
                              void* d_out, int out_size) {
    const float* x   = (const float*)d_in[0];
    const int*   ei  = (const int*)d_in[1];   // int32 or int64 (auto-detected)
    const int*   et  = (const int*)d_in[2];
    const float* emb = (const float*)d_in[3];
    const float* W1  = (const float*)d_in[4];
    const float* as1 = (const float*)d_in[5];
    const float* ad1 = (const float*)d_in[6];
    const float* b1  = (const float*)d_in[7];
    const float* g1  = (const float*)d_in[8];
    const float* be1 = (const float*)d_in[9];
    const float* W2  = (const float*)d_in[10];
    const float* as2 = (const float*)d_in[11];
    const float* ad2 = (const float*)d_in[12];
    const float* b2  = (const float*)d_in[13];
    const float* g2  = (const float*)d_in[14];
    const float* be2 = (const float*)d_in[15];
    float* out = (float*)d_out;

    k_detect<<<1, 256>>>(ei);
    k_convert<<<(EE + 255) / 256, 256>>>(ei, et);
    k_init<<<(NN * HIDD + 255) / 256, 256>>>(out);
    k_winner<<<(EE + 255) / 256, 256>>>();
    k_embw<<<RELS, HIDD>>>(emb, W1);

    dim3 grid1(HIDD / 128, (NN + 127) / 128);
    k_gemm1<<<grid1, 256>>>(x, W1);

    k_logits1<<<NN, 128>>>(as1, ad1);
    k_max1<<<(EE * NHEAD + 255) / 256, 256>>>();
    k_sum1<<<(EE * NHEAD + 255) / 256, 256>>>();
    k_agg1<<<EE, HIDD>>>();
    k_ln1<<<(NN + 3) / 4, 128>>>(b1, g1, be1);

    dim3 grid2(1, (NN + 127) / 128);
    k_gemm2<<<grid2, 256>>>(W2);

    k_logits2<<<(NN + 3) / 4, 128>>>(as2, ad2);
    k_max2<<<(EE + 255) / 256, 256>>>();
    k_sum2<<<(EE + 255) / 256, 256>>>();
    k_agg2<<<(EE * OUTD + 255) / 256, 256>>>(out);
    k_ln2<<<(NN + 3) / 4, 128>>>(b2, g2, be2, out);
}